// round 8
// baseline (speedup 1.0000x reference)
#include <cuda_runtime.h>
#include <cuda_bf16.h>
#include <cstdint>

#define B_ 32
#define T_ 4096
#define H_ 512
#define GRID_ 128
#define THREADS_ 256

// h image: [buf][n][k] bf16 bits. n: 0-31 = h_hi per batch, 32-63 = h_lo. k = hidden unit.
__device__ __align__(128) unsigned short g_Bimg[2][64][512];
__device__ float    g_xT[T_ * B_];
__device__ unsigned g_count;

__device__ __forceinline__ uint32_t ldcg_u32(const void* p) {
    uint32_t v; asm volatile("ld.global.cg.b32 %0, [%1];" : "=r"(v) : "l"(p)); return v;
}
__device__ __forceinline__ void stcg_u16(unsigned short* p, unsigned short v) {
    asm volatile("st.global.cg.u16 [%0], %1;" :: "l"(p), "h"(v));
}
__device__ __forceinline__ unsigned ld_acq(const unsigned* p) {
    unsigned v; asm volatile("ld.acquire.gpu.global.u32 %0, [%1];" : "=r"(v) : "l"(p)); return v;
}
__device__ __forceinline__ void red_rel_add1(unsigned* p) {
    asm volatile("red.release.gpu.global.add.u32 [%0], 1;" :: "l"(p));
}
__device__ __forceinline__ unsigned ld_acq_cta(const unsigned* p) {
    unsigned v; asm volatile("ld.acquire.cta.u32 %0, [%1];" : "=r"(v) : "l"(p)); return v;
}
__device__ __forceinline__ void st_rel_cta(unsigned* p, unsigned v) {
    asm volatile("st.release.cta.u32 [%0], %1;" :: "l"(p), "r"(v));
}
__device__ __forceinline__ float fsig(float x) {
    return __fdividef(1.0f, 1.0f + __expf(-x));
}
__device__ __forceinline__ float ftanh(float x) {
    return 1.0f - __fdividef(2.0f, 1.0f + __expf(2.0f * x));
}
__device__ __forceinline__ uint32_t pack2(__nv_bfloat16 e0, __nv_bfloat16 e1) {
    unsigned short s0 = *(unsigned short*)&e0, s1 = *(unsigned short*)&e1;
    return (uint32_t)s0 | ((uint32_t)s1 << 16);
}

#define HMMA(d, a, b0r, b1r) \
    asm volatile("mma.sync.aligned.m16n8k16.row.col.f32.bf16.bf16.f32 " \
        "{%0,%1,%2,%3}, {%4,%5,%6,%7}, {%8,%9}, {%0,%1,%2,%3};" \
        : "+f"(d[0]), "+f"(d[1]), "+f"(d[2]), "+f"(d[3]) \
        : "r"(a[0]), "r"(a[1]), "r"(a[2]), "r"(a[3]), "r"(b0r), "r"(b1r))

__global__ void init_kernel(const float* __restrict__ x) {
    int idx = blockIdx.x * blockDim.x + threadIdx.x;
    int stride = gridDim.x * blockDim.x;
    unsigned* bz = (unsigned*)&g_Bimg[0][0][0];
    for (int i = idx; i < 64 * 512 / 2; i += stride) bz[i] = 0u;   // h(-1) = 0
    for (int i = idx; i < T_ * B_; i += stride) {
        int t = i >> 5, b = i & 31;
        g_xT[i] = x[(size_t)b * T_ + t];
    }
    if (idx == 0) g_count = 0u;
}

__global__ void __launch_bounds__(THREADS_, 1) lstm_kernel(
    const float* __restrict__ Wih,
    const float* __restrict__ Whh,
    const float* __restrict__ bih,
    const float* __restrict__ bhh,
    float* __restrict__ out,
    int write_final)
{
    __shared__ float sPart[2][4][16][33];  // [buf][ki][gate-row][batch(+pad)]
    __shared__ float sOut[128];            // [b][u]
    __shared__ unsigned s_gen;

    const int tid  = threadIdx.x;
    const int warp = tid >> 5;
    const int lane = tid & 31;
    const int g    = lane >> 2;   // groupID in fragment
    const int tq   = lane & 3;    // threadID_in_group
    const int cta  = blockIdx.x;
    const int ni   = warp & 1;    // N-half (16 folded cols each)
    const int ki   = warp >> 1;   // K-split 0..3 (K128 each)
    const int kbase = ki * 128;

    // ---- prologue: W_hh slice -> resident A fragments (hi rows mt=0, lo rows mt=1) ----
    // A fragment mapping (m16n8k16): reg0=(row g, k 2t,2t+1) reg1=(row g+8) reg2=(row g, k+8) reg3=(row g+8, k+8)
    uint32_t A[2][8][4];
#pragma unroll
    for (int mt = 0; mt < 2; mt++) {
#pragma unroll
        for (int kt = 0; kt < 8; kt++) {
            int k0 = kbase + kt * 16 + 2 * tq;
#pragma unroll
            for (int rg = 0; rg < 4; rg++) {
                int gr = (rg & 1) ? g + 8 : g;          // gate row 0..15
                int kk = k0 + ((rg >> 1) ? 8 : 0);
                int q = gr >> 2, u = gr & 3;
                const float* wp = &Whh[(size_t)(q * H_ + cta * 4 + u) * H_ + kk];
                float w0 = wp[0], w1 = wp[1];
                __nv_bfloat16 h0 = __float2bfloat16(w0);
                __nv_bfloat16 h1 = __float2bfloat16(w1);
                if (mt) {
                    h0 = __float2bfloat16(w0 - __bfloat162float(h0));
                    h1 = __float2bfloat16(w1 - __bfloat162float(h1));
                }
                A[mt][kt][rg] = pack2(h0, h1);
            }
        }
    }

    // pointwise constants + persistent state (consumers: tid<128 -> u=warp, b=lane)
    const int u = warp;       // valid when tid<128
    const int b = lane;
    const int gu = cta * 4 + u;
    float wih[4], bias[4];
    float h_loc = 0.0f, c_loc = 0.0f;
    if (tid < 128) {
#pragma unroll
        for (int q = 0; q < 4; q++) {
            wih[q]  = Wih[q * H_ + gu];
            bias[q] = bih[q * H_ + gu] + bhh[q * H_ + gu];
        }
    }
    if (tid == 0) s_gen = 0u;
    __syncthreads();

    // B-fragment n column bases for this warp's 4 n-tiles (pairs nt<->nt+2 are c and c+32)
    const int colN0 = 16 * ni;
    const int colN[4] = { colN0, colN0 + 8, 32 + colN0, 40 + colN0 };

    for (int t = 0; t < T_; t++) {
        const int p = t & 1;

        // ---- step gate: warp7 lane0 polls global, relays via smem ----
        if (warp == 7 && lane == 0) {
            while (ld_acq(&g_count) < (unsigned)GRID_ * (unsigned)t) { }
            st_rel_cta(&s_gen, (unsigned)t);
        }
        while (ld_acq_cta(&s_gen) < (unsigned)t) { }

        float xv = 0.0f;
        if (tid < 128) xv = g_xT[t * B_ + b];

        // ---- load B fragments from global h image (L2) ----
        // B mapping: reg0 = k rows {2t,2t+1}, reg1 = {2t+8,2t+9}, col n = colN+g
        const unsigned char* img = (const unsigned char*)&g_Bimg[p][0][0];
        uint32_t Bv[4][8][2];
#pragma unroll
        for (int nt = 0; nt < 4; nt++) {
            const unsigned char* pb = img + (size_t)(colN[nt] + g) * 1024 + (kbase + 2 * tq) * 2;
#pragma unroll
            for (int kt = 0; kt < 8; kt++) {
                Bv[nt][kt][0] = ldcg_u32(pb + kt * 32);
                Bv[nt][kt][1] = ldcg_u32(pb + kt * 32 + 16);
            }
        }

        // ---- MMA: D[mt][nt] (M16 x N8 tiles), K128 accumulate ----
        float D[2][4][4];
#pragma unroll
        for (int mt = 0; mt < 2; mt++)
#pragma unroll
            for (int nt = 0; nt < 4; nt++)
#pragma unroll
                for (int e = 0; e < 4; e++) D[mt][nt][e] = 0.0f;
#pragma unroll
        for (int kt = 0; kt < 8; kt++)
#pragma unroll
            for (int mt = 0; mt < 2; mt++)
#pragma unroll
                for (int nt = 0; nt < 4; nt++)
                    HMMA(D[mt][nt], A[mt][kt], Bv[nt][kt][0], Bv[nt][kt][1]);

        // ---- fold hi/lo rows (mt) and hhi/hlo cols (nt pairs) in registers, STS ----
#pragma unroll
        for (int j = 0; j < 2; j++) {
            float f0 = (D[0][j][0] + D[1][j][0]) + (D[0][j + 2][0] + D[1][j + 2][0]);
            float f1 = (D[0][j][1] + D[1][j][1]) + (D[0][j + 2][1] + D[1][j + 2][1]);
            float f2 = (D[0][j][2] + D[1][j][2]) + (D[0][j + 2][2] + D[1][j + 2][2]);
            float f3 = (D[0][j][3] + D[1][j][3]) + (D[0][j + 2][3] + D[1][j + 2][3]);
            int colb = colN0 + 8 * j + 2 * tq;
            sPart[p][ki][g][colb]         = f0;
            sPart[p][ki][g][colb + 1]     = f1;
            sPart[p][ki][g + 8][colb]     = f2;
            sPart[p][ki][g + 8][colb + 1] = f3;
        }

        if (warp >= 4) {
            // producers: signal and run ahead to step t+1
            asm volatile("bar.arrive 2, %0;" :: "n"(THREADS_) : "memory");
        } else {
            asm volatile("bar.sync 2, %0;" :: "n"(THREADS_) : "memory");

            // ---- reduce over 4 k-splits + pointwise ----
            float g4[4];
#pragma unroll
            for (int q = 0; q < 4; q++) {
                int r = q * 4 + u;
                g4[q] = (sPart[p][0][r][b] + sPart[p][1][r][b])
                      + (sPart[p][2][r][b] + sPart[p][3][r][b])
                      + fmaf(xv, wih[q], bias[q]);
            }
            float is = fsig(g4[0]);
            float fs = fsig(g4[1]);
            float gs = ftanh(g4[2]);
            float os = fsig(g4[3]);
            float cn = fs * c_loc + is * gs;
            float hn = os * ftanh(cn);
            h_loc = 0.5f * (h_loc + hn);
            c_loc = 0.5f * (c_loc + cn);

            // publish h as bf16 hi/lo into next h image
            __nv_bfloat16 hh = __float2bfloat16(h_loc);
            __nv_bfloat16 hl = __float2bfloat16(h_loc - __bfloat162float(hh));
            stcg_u16(&g_Bimg[p ^ 1][b][gu],      *(unsigned short*)&hh);
            stcg_u16(&g_Bimg[p ^ 1][32 + b][gu], *(unsigned short*)&hl);
            sOut[b * 4 + u] = h_loc;

            if (write_final && t == T_ - 1) {
                float* o2 = out + (size_t)B_ * T_ * H_;
                o2[b * (2 * H_) + gu]      = h_loc;
                o2[b * (2 * H_) + H_ + gu] = c_loc;
            }

            asm volatile("bar.sync 1, 128;" ::: "memory");
            if (tid == 0) { __threadfence(); red_rel_add1(&g_count); }

            if (tid < 32) {  // coalesced v4 output store (off critical path)
                const float4 v = *(const float4*)(sOut + tid * 4);
                float* dst = out + ((size_t)tid * T_ + t) * H_ + cta * 4;
                asm volatile("st.global.cs.v4.f32 [%0], {%1,%2,%3,%4};"
                             :: "l"(dst), "f"(v.x), "f"(v.y), "f"(v.z), "f"(v.w));
            }
        }
    }
}

extern "C" void kernel_launch(void* const* d_in, const int* in_sizes, int n_in,
                              void* d_out, int out_size)
{
    const float* x   = (const float*)d_in[0];
    const float* Wih = (const float*)d_in[1];
    const float* Whh = (const float*)d_in[2];
    const float* bih = (const float*)d_in[3];
    const float* bhh = (const float*)d_in[4];
    float* out = (float*)d_out;

    int need = B_ * T_ * H_ + B_ * 2 * H_;
    int write_final = (out_size >= need) ? 1 : 0;

    init_kernel<<<256, 512>>>(x);
    lstm_kernel<<<GRID_, THREADS_>>>(Wih, Whh, bih, bhh, out, write_final);
}

// round 9
// speedup vs baseline: 1.6703x; 1.6703x over previous
#include <cuda_runtime.h>
#include <cuda_bf16.h>
#include <cstdint>

#define B_ 32
#define T_ 4096
#define H_ 512
#define GRID_ 128
#define THREADS_ 256

// h image: [buf][n][k] bf16 bits. n: 0-31 = h_hi per batch, 32-63 = h_lo. k = hidden unit.
__device__ __align__(128) unsigned short g_Bimg[2][64][512];
__device__ float    g_xT[T_ * B_];
__device__ unsigned g_count;

__device__ __forceinline__ uint4 ldcg_v4(const void* p) {
    uint4 v;
    asm volatile("ld.global.cg.v4.b32 {%0,%1,%2,%3}, [%4];"
                 : "=r"(v.x), "=r"(v.y), "=r"(v.z), "=r"(v.w) : "l"(p));
    return v;
}
__device__ __forceinline__ void stcg_u16(unsigned short* p, unsigned short v) {
    asm volatile("st.global.cg.u16 [%0], %1;" :: "l"(p), "h"(v));
}
__device__ __forceinline__ unsigned ld_acq(const unsigned* p) {
    unsigned v; asm volatile("ld.acquire.gpu.global.u32 %0, [%1];" : "=r"(v) : "l"(p)); return v;
}
__device__ __forceinline__ void red_rel_add1(unsigned* p) {
    asm volatile("red.release.gpu.global.add.u32 [%0], 1;" :: "l"(p));
}
__device__ __forceinline__ unsigned ld_acq_cta(const unsigned* p) {
    unsigned v; asm volatile("ld.acquire.cta.u32 %0, [%1];" : "=r"(v) : "l"(p)); return v;
}
__device__ __forceinline__ void st_rel_cta(unsigned* p, unsigned v) {
    asm volatile("st.release.cta.u32 [%0], %1;" :: "l"(p), "r"(v));
}
__device__ __forceinline__ float fsig(float x) {
    return __fdividef(1.0f, 1.0f + __expf(-x));
}
__device__ __forceinline__ float ftanh(float x) {
    return 1.0f - __fdividef(2.0f, 1.0f + __expf(2.0f * x));
}
__device__ __forceinline__ uint32_t pack2(__nv_bfloat16 e0, __nv_bfloat16 e1) {
    unsigned short s0 = *(unsigned short*)&e0, s1 = *(unsigned short*)&e1;
    return (uint32_t)s0 | ((uint32_t)s1 << 16);
}
__device__ __forceinline__ uint32_t lds32(uint32_t a) {
    uint32_t v; asm volatile("ld.shared.b32 %0, [%1];" : "=r"(v) : "r"(a)); return v;
}
__device__ __forceinline__ uint32_t smem_u32(const void* p) {
    uint32_t a;
    asm("{ .reg .u64 t; cvta.to.shared.u64 t, %1; cvt.u32.u64 %0, t; }" : "=r"(a) : "l"(p));
    return a;
}

#define HMMA(d, a, b0r, b1r) \
    asm volatile("mma.sync.aligned.m16n8k16.row.col.f32.bf16.bf16.f32 " \
        "{%0,%1,%2,%3}, {%4,%5,%6,%7}, {%8,%9}, {%0,%1,%2,%3};" \
        : "+f"(d[0]), "+f"(d[1]), "+f"(d[2]), "+f"(d[3]) \
        : "r"(a[0]), "r"(a[1]), "r"(a[2]), "r"(a[3]), "r"(b0r), "r"(b1r))

// per-warp staging region: 32 rows x 272B (padded; bank = 4g+tq conflict-free)
#define WPITCH 272
#define WREG   (32 * WPITCH)   // 8704 B per warp
#define DYN_SMEM (8 * WREG)    // 69632 B

__global__ void init_kernel(const float* __restrict__ x) {
    int idx = blockIdx.x * blockDim.x + threadIdx.x;
    int stride = gridDim.x * blockDim.x;
    unsigned* bz = (unsigned*)&g_Bimg[0][0][0];
    for (int i = idx; i < 64 * 512 / 2; i += stride) bz[i] = 0u;   // h(-1) = 0
    for (int i = idx; i < T_ * B_; i += stride) {
        int t = i >> 5, b = i & 31;
        g_xT[i] = x[(size_t)b * T_ + t];
    }
    if (idx == 0) g_count = 0u;
}

__global__ void __launch_bounds__(THREADS_, 1) lstm_kernel(
    const float* __restrict__ Wih,
    const float* __restrict__ Whh,
    const float* __restrict__ bih,
    const float* __restrict__ bhh,
    float* __restrict__ out,
    int write_final)
{
    extern __shared__ unsigned char dyn[];
    __shared__ float sPart[2][4][16][33];  // [buf][ki][gate-row][batch(+pad)]
    __shared__ float sOut[128];            // [b][u]
    __shared__ unsigned s_gen;

    const int tid  = threadIdx.x;
    const int warp = tid >> 5;
    const int lane = tid & 31;
    const int g    = lane >> 2;   // groupID in fragment
    const int tq   = lane & 3;    // threadID_in_group
    const int cta  = blockIdx.x;
    const int ni   = warp & 1;    // N-half (16 folded cols each)
    const int ki   = warp >> 1;   // K-split 0..3 (K128 each)
    const int kbase = ki * 128;

    const uint32_t wreg = smem_u32(dyn) + warp * WREG;   // this warp's staging base

    // ---- prologue: W_hh slice -> resident A fragments (hi set mt=0, lo set mt=1) ----
    uint32_t A[2][8][4];
#pragma unroll
    for (int mt = 0; mt < 2; mt++) {
#pragma unroll
        for (int kt = 0; kt < 8; kt++) {
            int k0 = kbase + kt * 16 + 2 * tq;
#pragma unroll
            for (int rg = 0; rg < 4; rg++) {
                int gr = (rg & 1) ? g + 8 : g;          // gate row 0..15
                int kk = k0 + ((rg >> 1) ? 8 : 0);
                int q = gr >> 2, u = gr & 3;
                const float* wp = &Whh[(size_t)(q * H_ + cta * 4 + u) * H_ + kk];
                float w0 = wp[0], w1 = wp[1];
                __nv_bfloat16 h0 = __float2bfloat16(w0);
                __nv_bfloat16 h1 = __float2bfloat16(w1);
                if (mt) {
                    h0 = __float2bfloat16(w0 - __bfloat162float(h0));
                    h1 = __float2bfloat16(w1 - __bfloat162float(h1));
                }
                A[mt][kt][rg] = pack2(h0, h1);
            }
        }
    }

    // pointwise constants + persistent state (consumers: tid<128 -> u=warp, b=lane)
    const int u = warp;
    const int b = lane;
    const int gu = cta * 4 + u;
    float wih[4], bias[4];
    float h_loc = 0.0f, c_loc = 0.0f;
    if (tid < 128) {
#pragma unroll
        for (int q = 0; q < 4; q++) {
            wih[q]  = Wih[q * H_ + gu];
            bias[q] = bih[q * H_ + gu] + bhh[q * H_ + gu];
        }
    }
    if (tid == 0) s_gen = 0u;
    __syncthreads();

    // staging-row -> global n column: rows 0-15 -> 16ni+r (hhi block of this half),
    // rows 16-31 -> 32+16ni+(r-16) (hlo block)
    const int lrow = (lane >> 4);          // 0 or 1 (which of the 2 rows this lane copies)
    const int loff = (lane & 15) * 16;     // byte offset within 256B row slice

    for (int t = 0; t < T_; t++) {
        const int p = t & 1;

        // ---- step gate: warp7 lane0 polls global, relays via smem ----
        if (warp == 7 && lane == 0) {
            while (ld_acq(&g_count) < (unsigned)GRID_ * (unsigned)t) { }
            st_rel_cta(&s_gen, (unsigned)t);
        }
        while (ld_acq_cta(&s_gen) < (unsigned)t) { }

        float xv = 0.0f;
        if (tid < 128) xv = g_xT[t * B_ + b];

        // ---- stage this warp's 8KB B slice: coalesced LDG.128 -> padded smem ----
        const unsigned char* img = (const unsigned char*)&g_Bimg[p][0][0];
#pragma unroll
        for (int it = 0; it < 16; it++) {
            int nrow = it * 2 + lrow;                       // 0..31
            int n = (nrow < 16) ? (16 * ni + nrow) : (16 + 16 * ni + nrow);
            uint4 v = ldcg_v4(img + (size_t)n * 1024 + kbase * 2 + loff);
            *(uint4*)((unsigned char*)dyn + warp * WREG + nrow * WPITCH + loff) = v;
        }
        __syncwarp();

        // ---- MMA: stream B from smem (conflict-free), K128 accumulate ----
        float D[2][4][4];
#pragma unroll
        for (int mt = 0; mt < 2; mt++)
#pragma unroll
            for (int nt = 0; nt < 4; nt++)
#pragma unroll
                for (int e = 0; e < 4; e++) D[mt][nt][e] = 0.0f;

#pragma unroll
        for (int kt = 0; kt < 8; kt++) {
            uint32_t Bv[4][2];
#pragma unroll
            for (int nt = 0; nt < 4; nt++) {
                uint32_t a = wreg + (nt * 8 + g) * WPITCH + kt * 32 + tq * 4;
                Bv[nt][0] = lds32(a);
                Bv[nt][1] = lds32(a + 16);
            }
#pragma unroll
            for (int mt = 0; mt < 2; mt++)
#pragma unroll
                for (int nt = 0; nt < 4; nt++)
                    HMMA(D[mt][nt], A[mt][kt], Bv[nt][kt ? 0 : 0], Bv[nt][1]);
        }

        // ---- fold hi/lo A-sets (mt) and hhi/hlo col pairs (nt vs nt+2), STS ----
#pragma unroll
        for (int j = 0; j < 2; j++) {
            float f0 = (D[0][j][0] + D[1][j][0]) + (D[0][j + 2][0] + D[1][j + 2][0]);
            float f1 = (D[0][j][1] + D[1][j][1]) + (D[0][j + 2][1] + D[1][j + 2][1]);
            float f2 = (D[0][j][2] + D[1][j][2]) + (D[0][j + 2][2] + D[1][j + 2][2]);
            float f3 = (D[0][j][3] + D[1][j][3]) + (D[0][j + 2][3] + D[1][j + 2][3]);
            int colb = 16 * ni + 8 * j + 2 * tq;
            sPart[p][ki][g][colb]         = f0;
            sPart[p][ki][g][colb + 1]     = f1;
            sPart[p][ki][g + 8][colb]     = f2;
            sPart[p][ki][g + 8][colb + 1] = f3;
        }

        if (warp >= 4) {
            // producers: signal and run ahead to step t+1
            asm volatile("bar.arrive 2, %0;" :: "n"(THREADS_) : "memory");
        } else {
            asm volatile("bar.sync 2, %0;" :: "n"(THREADS_) : "memory");

            // ---- reduce over 4 k-splits + pointwise ----
            float g4[4];
#pragma unroll
            for (int q = 0; q < 4; q++) {
                int r = q * 4 + u;
                g4[q] = (sPart[p][0][r][b] + sPart[p][1][r][b])
                      + (sPart[p][2][r][b] + sPart[p][3][r][b])
                      + fmaf(xv, wih[q], bias[q]);
            }
            float is = fsig(g4[0]);
            float fs = fsig(g4[1]);
            float gs = ftanh(g4[2]);
            float os = fsig(g4[3]);
            float cn = fs * c_loc + is * gs;
            float hn = os * ftanh(cn);
            h_loc = 0.5f * (h_loc + hn);
            c_loc = 0.5f * (c_loc + cn);

            // publish h as bf16 hi/lo into next h image
            __nv_bfloat16 hh = __float2bfloat16(h_loc);
            __nv_bfloat16 hl = __float2bfloat16(h_loc - __bfloat162float(hh));
            stcg_u16(&g_Bimg[p ^ 1][b][gu],      *(unsigned short*)&hh);
            stcg_u16(&g_Bimg[p ^ 1][32 + b][gu], *(unsigned short*)&hl);
            sOut[b * 4 + u] = h_loc;

            if (write_final && t == T_ - 1) {
                float* o2 = out + (size_t)B_ * T_ * H_;
                o2[b * (2 * H_) + gu]      = h_loc;
                o2[b * (2 * H_) + H_ + gu] = c_loc;
            }

            asm volatile("bar.sync 1, 128;" ::: "memory");
            if (tid == 0) red_rel_add1(&g_count);

            if (tid < 32) {  // coalesced v4 output store (off critical path)
                const float4 v = *(const float4*)(sOut + tid * 4);
                float* dst = out + ((size_t)tid * T_ + t) * H_ + cta * 4;
                asm volatile("st.global.cs.v4.f32 [%0], {%1,%2,%3,%4};"
                             :: "l"(dst), "f"(v.x), "f"(v.y), "f"(v.z), "f"(v.w));
            }
        }
    }
}

extern "C" void kernel_launch(void* const* d_in, const int* in_sizes, int n_in,
                              void* d_out, int out_size)
{
    const float* x   = (const float*)d_in[0];
    const float* Wih = (const float*)d_in[1];
    const float* Whh = (const float*)d_in[2];
    const float* bih = (const float*)d_in[3];
    const float* bhh = (const float*)d_in[4];
    float* out = (float*)d_out;

    int need = B_ * T_ * H_ + B_ * 2 * H_;
    int write_final = (out_size >= need) ? 1 : 0;

    static int smem_set = 0;
    if (!smem_set) {
        cudaFuncSetAttribute(lstm_kernel,
                             cudaFuncAttributeMaxDynamicSharedMemorySize,
                             DYN_SMEM);
        smem_set = 1;
    }

    init_kernel<<<256, 512>>>(x);
    lstm_kernel<<<GRID_, THREADS_, DYN_SMEM>>>(Wih, Whh, bih, bhh, out, write_final);
}